// round 2
// baseline (speedup 1.0000x reference)
#include <cuda_runtime.h>

#define Bn 256
#define Tn 256
#define Hn 1024
#define G4 4096
#define Dn 409
#define DP 416          // D padded to mult of 16
#define KK 1440         // Hn + DP, = 90 * 16

// ---------------- scratch (static, 16B aligned for vector access) -------------
__device__ __align__(16) float g_xT[Tn * Bn * DP];     // 109 MB [t][b][dp]
__device__ __align__(16) float g_Wcat[G4 * KK];        // 23.6 MB [n][k] = [Whh | Wih pad]
__device__ __align__(16) float g_gates[Bn * G4];       // 4 MB
__device__ __align__(16) float g_h[2][Bn * Hn];        // 2 MB
__device__ __align__(16) float g_c[Bn * Hn];           // 1 MB

// ---------------- packed f32x2 helpers ----------------------------------------
__device__ __forceinline__ void ffma2(unsigned long long &d, unsigned long long a,
                                      unsigned long long b) {
    asm("fma.rn.f32x2 %0, %1, %2, %0;" : "+l"(d) : "l"(a), "l"(b));
}
__device__ __forceinline__ unsigned long long pk2(float x, float y) {
    unsigned long long r;
    asm("mov.b64 %0, {%1, %2};" : "=l"(r) : "f"(x), "f"(y));
    return r;
}
__device__ __forceinline__ float2 up2(unsigned long long v) {
    float2 r;
    asm("mov.b64 {%0, %1}, %2;" : "=f"(r.x), "=f"(r.y) : "l"(v));
    return r;
}

// ---------------- prep kernels -------------------------------------------------
// g_xT[t][b][d] = concat(x_text, x_audio, x_vision)[b][t][d], zero-padded to DP
__global__ void prep_x(const float* __restrict__ xt,
                       const float* __restrict__ xa,
                       const float* __restrict__ xv) {
    int idx = blockIdx.x * blockDim.x + threadIdx.x;
    if (idx >= Tn * Bn * DP) return;
    int d = idx % DP;
    int r = idx / DP;            // r = t*Bn + b
    int b = r % Bn;
    int t = r / Bn;
    int bt = b * Tn + t;
    float v = 0.f;
    if (d < 300)       v = xt[bt * 300 + d];
    else if (d < 374)  v = xa[bt * 74 + (d - 300)];
    else if (d < 409)  v = xv[bt * 35 + (d - 374)];
    g_xT[idx] = v;
}

// g_Wcat[n][k] : k<1024 -> W_hh[n][k] ; else d=k-1024: d<409 -> W_ih[n][d] : 0
__global__ void prep_w(const float* __restrict__ Whh, const float* __restrict__ Wih) {
    int idx = blockIdx.x * blockDim.x + threadIdx.x;
    if (idx >= G4 * KK) return;
    int k = idx % KK;
    int n = idx / KK;
    float v;
    if (k < Hn) {
        v = Whh[n * Hn + k];
    } else {
        int d = k - Hn;
        v = (d < Dn) ? Wih[n * Dn + d] : 0.f;
    }
    g_Wcat[idx] = v;
}

__global__ void init_state() {
    int idx = blockIdx.x * blockDim.x + threadIdx.x;
    if (idx < Bn * Hn) { g_h[0][idx] = 0.f; g_c[idx] = 0.f; }
}

// ---------------- per-step GEMM: gates = [h | x_t] @ Wcat^T --------------------
// M=256, N=4096, K=1440.  BM=BN=64, BK=16, 128 threads, 8x4 micro (f32x2).
// A is stored duplicated in SMEM so FFMA2 operand pairs come free.
__global__ __launch_bounds__(128)
void step_gemm(int t, int hin) {
    __shared__ __align__(16) float As2[16][132];   // As2[k][2m],[2m+1] = A[m][k]
    __shared__ __align__(16) float Bs[16][68];     // Bs[k][n]
    const int n0 = blockIdx.x * 64;
    const int m0 = blockIdx.y * 64;
    const int tid = threadIdx.x;
    const int tn = tid & 15;         // 0..15 : n-group (4 cols)
    const int tm = tid >> 4;         // 0..7  : m-group (8 rows)
    const int lrow = tid >> 2;       // 0..31 : load row
    const int lcol = (tid & 3) << 2; // 0,4,8,12 : load col (k within tile)

    unsigned long long acc[8][2];
#pragma unroll
    for (int i = 0; i < 8; i++) { acc[i][0] = 0ULL; acc[i][1] = 0ULL; }

    const float* __restrict__ hsrc = g_h[hin];

    for (int kt = 0; kt < KK / 16; kt++) {
        const int kk = kt * 16 + lcol;     // global k of this thread's float4
        float4 a0, a1, b0, b1;
        if (kk < Hn) {
            a0 = *(const float4*)&hsrc[(m0 + lrow) * Hn + kk];
            a1 = *(const float4*)&hsrc[(m0 + lrow + 32) * Hn + kk];
        } else {
            const int d = kk - Hn;
            a0 = *(const float4*)&g_xT[(t * Bn + m0 + lrow) * DP + d];
            a1 = *(const float4*)&g_xT[(t * Bn + m0 + lrow + 32) * DP + d];
        }
        b0 = *(const float4*)&g_Wcat[(n0 + lrow) * KK + kk];
        b1 = *(const float4*)&g_Wcat[(n0 + lrow + 32) * KK + kk];

        __syncthreads();
        {
            float va0[4] = {a0.x, a0.y, a0.z, a0.w};
            float va1[4] = {a1.x, a1.y, a1.z, a1.w};
            float vb0[4] = {b0.x, b0.y, b0.z, b0.w};
            float vb1[4] = {b1.x, b1.y, b1.z, b1.w};
#pragma unroll
            for (int j = 0; j < 4; j++) {
                *(unsigned long long*)&As2[lcol + j][2 * lrow]        = pk2(va0[j], va0[j]);
                *(unsigned long long*)&As2[lcol + j][2 * (lrow + 32)] = pk2(va1[j], va1[j]);
                Bs[lcol + j][lrow]      = vb0[j];
                Bs[lcol + j][lrow + 32] = vb1[j];
            }
        }
        __syncthreads();

#pragma unroll
        for (int k = 0; k < 16; k++) {
            ulonglong2 aA = *(const ulonglong2*)&As2[k][tm * 16];
            ulonglong2 aB = *(const ulonglong2*)&As2[k][tm * 16 + 4];
            ulonglong2 aC = *(const ulonglong2*)&As2[k][tm * 16 + 8];
            ulonglong2 aD = *(const ulonglong2*)&As2[k][tm * 16 + 12];
            ulonglong2 bb = *(const ulonglong2*)&Bs[k][tn * 4];
            ffma2(acc[0][0], aA.x, bb.x); ffma2(acc[0][1], aA.x, bb.y);
            ffma2(acc[1][0], aA.y, bb.x); ffma2(acc[1][1], aA.y, bb.y);
            ffma2(acc[2][0], aB.x, bb.x); ffma2(acc[2][1], aB.x, bb.y);
            ffma2(acc[3][0], aB.y, bb.x); ffma2(acc[3][1], aB.y, bb.y);
            ffma2(acc[4][0], aC.x, bb.x); ffma2(acc[4][1], aC.x, bb.y);
            ffma2(acc[5][0], aC.y, bb.x); ffma2(acc[5][1], aC.y, bb.y);
            ffma2(acc[6][0], aD.x, bb.x); ffma2(acc[6][1], aD.x, bb.y);
            ffma2(acc[7][0], aD.y, bb.x); ffma2(acc[7][1], aD.y, bb.y);
        }
    }

#pragma unroll
    for (int i = 0; i < 8; i++) {
        const int row = m0 + tm * 8 + i;
        float2 v0 = up2(acc[i][0]);
        float2 v1 = up2(acc[i][1]);
        *(float4*)&g_gates[row * G4 + n0 + tn * 4] = make_float4(v0.x, v0.y, v1.x, v1.y);
    }
}

// ---------------- LSTM elementwise update (biases folded here) -----------------
__device__ __forceinline__ float sigf(float x) { return 1.f / (1.f + expf(-x)); }

__global__ void update_kernel(const float* __restrict__ bih,
                              const float* __restrict__ bhh, int hout) {
    int idx = blockIdx.x * blockDim.x + threadIdx.x;   // exactly B*H threads
    int bb = idx >> 10;
    int k = idx & 1023;
    const float* gr = g_gates + bb * G4 + k;
    float iv = sigf(gr[0]        + bih[k]          + bhh[k]);
    float fv = sigf(gr[Hn]       + bih[Hn + k]     + bhh[Hn + k]);
    float gv = tanhf(gr[2 * Hn]  + bih[2 * Hn + k] + bhh[2 * Hn + k]);
    float ov = sigf(gr[3 * Hn]   + bih[3 * Hn + k] + bhh[3 * Hn + k]);
    float c = fv * g_c[idx] + iv * gv;
    g_c[idx] = c;
    g_h[hout][idx] = ov * tanhf(c);
}

// ---------------- MLP head: relu(h @ W1^T + b1) @ W2^T + b2 --------------------
__global__ __launch_bounds__(256)
void mlp_kernel(const float* __restrict__ W1, const float* __restrict__ b1,
                const float* __restrict__ W2, const float* __restrict__ b2,
                float* __restrict__ out, int hin) {
    __shared__ __align__(16) float hs[Hn];
    __shared__ float hid[512];
    __shared__ float red[256];
    int bb = blockIdx.x, tid = threadIdx.x;
    for (int i = tid; i < Hn; i += 256) hs[i] = g_h[hin][bb * Hn + i];
    __syncthreads();
    for (int j = tid; j < 512; j += 256) {
        const float4* w = (const float4*)(W1 + j * Hn);
        float s = 0.f;
#pragma unroll 8
        for (int k = 0; k < Hn / 4; k++) {
            float4 w4 = w[k];
            s += w4.x * hs[4 * k] + w4.y * hs[4 * k + 1] + w4.z * hs[4 * k + 2] + w4.w * hs[4 * k + 3];
        }
        s += b1[j];
        hid[j] = s > 0.f ? s : 0.f;
    }
    __syncthreads();
    red[tid] = hid[tid] * W2[tid] + hid[tid + 256] * W2[tid + 256];
    __syncthreads();
    for (int s = 128; s > 0; s >>= 1) {
        if (tid < s) red[tid] += red[tid + s];
        __syncthreads();
    }
    if (tid == 0) out[bb] = red[0] + b2[0];
}

// ---------------- launch -------------------------------------------------------
extern "C" void kernel_launch(void* const* d_in, const int* in_sizes, int n_in,
                              void* d_out, int out_size) {
    const float* x_text   = (const float*)d_in[0];
    const float* x_audio  = (const float*)d_in[1];
    const float* x_vision = (const float*)d_in[2];
    const float* W_ih     = (const float*)d_in[3];
    const float* W_hh     = (const float*)d_in[4];
    const float* b_ih     = (const float*)d_in[5];
    const float* b_hh     = (const float*)d_in[6];
    const float* W1       = (const float*)d_in[7];
    const float* b1       = (const float*)d_in[8];
    const float* W2       = (const float*)d_in[9];
    const float* b2       = (const float*)d_in[10];
    float* out = (float*)d_out;

    prep_x<<<(Tn * Bn * DP + 255) / 256, 256>>>(x_text, x_audio, x_vision);
    prep_w<<<(G4 * KK + 255) / 256, 256>>>(W_hh, W_ih);
    init_state<<<(Bn * Hn + 255) / 256, 256>>>();
    for (int t = 0; t < Tn; t++) {
        step_gemm<<<dim3(G4 / 64, Bn / 64), 128>>>(t, t & 1);
        update_kernel<<<Bn * Hn / 256, 256>>>(b_ih, b_hh, (t + 1) & 1);
    }
    mlp_kernel<<<Bn, 256>>>(W1, b1, W2, b2, out, 0);
}

// round 5
// speedup vs baseline: 1.8115x; 1.8115x over previous
#include <cuda_runtime.h>
#include <cuda_fp16.h>
#include <cstdint>

#define Bn 256
#define Tn 256
#define Hn 1024
#define G4 4096
#define Dn 409
#define KST 3072          // 3 * Hn   : [h_hi | h_lo | h_hi]
#define KXG 1280          // 3*416=1248 padded to 1280
#define MXG 65536         // B*T

// ---------------- device scratch (static; no allocation) ----------------------
__device__ __align__(16) __half g_W[(size_t)G4 * KST];      // 24 MB  [p][k] gate-interleaved
__device__ __align__(16) __half g_Wx[(size_t)G4 * KXG];     // 10 MB
__device__ __align__(16) __half g_xbf[(size_t)MXG * KXG];   // 160 MB [t*256+b][k]
__device__ float g_xg[(size_t)MXG * G4];                    // 1 GiB  [t*256+b][p]
__device__ __align__(16) __half g_hhi[2][Bn * Hn];
__device__ __align__(16) __half g_hlo[2][Bn * Hn];
__device__ float g_c[Bn * Hn];
__device__ float g_bias[G4];                                // permuted b_ih+b_hh

// ---------------- PTX helpers --------------------------------------------------
__device__ __forceinline__ uint32_t s2u(const void* p) {
    uint32_t a;
    asm("{ .reg .u64 t; cvta.to.shared.u64 t, %1; cvt.u32.u64 %0, t; }" : "=r"(a) : "l"(p));
    return a;
}
__device__ __forceinline__ void cp16(uint32_t dst, const void* src) {
    asm volatile("cp.async.cg.shared.global [%0], [%1], 16;" :: "r"(dst), "l"(src));
}
__device__ __forceinline__ void cp_commit() { asm volatile("cp.async.commit_group;"); }
__device__ __forceinline__ void cp_wait2() { asm volatile("cp.async.wait_group 2;" ::: "memory"); }

__device__ __forceinline__ void ldsm4(uint32_t& r0, uint32_t& r1, uint32_t& r2, uint32_t& r3,
                                      uint32_t addr) {
    asm volatile("ldmatrix.sync.aligned.m8n8.x4.shared.b16 {%0,%1,%2,%3}, [%4];"
                 : "=r"(r0), "=r"(r1), "=r"(r2), "=r"(r3) : "r"(addr));
}
__device__ __forceinline__ void mma16816(float* d, const uint32_t* a, uint32_t b0, uint32_t b1) {
    asm volatile(
        "mma.sync.aligned.m16n8k16.row.col.f32.f16.f16.f32 "
        "{%0,%1,%2,%3}, {%4,%5,%6,%7}, {%8,%9}, {%0,%1,%2,%3};"
        : "+f"(d[0]), "+f"(d[1]), "+f"(d[2]), "+f"(d[3])
        : "r"(a[0]), "r"(a[1]), "r"(a[2]), "r"(a[3]), "r"(b0), "r"(b1));
}

#define SW128(o) ((o) ^ (((o) >> 3) & 0x70))
#define STGB 24576        // per-stage: A 8KB + B 16KB
#define SMEMSZ (3 * STGB)

__device__ __forceinline__ float sigf(float x) { return 1.f / (1.f + expf(-x)); }

// ---------------- prep kernels -------------------------------------------------
// A-side split [hi | lo | hi], B-side [Whi | Whi | Wlo]
__global__ void prep_x(const float* __restrict__ xt, const float* __restrict__ xa,
                       const float* __restrict__ xv) {
    size_t idx = (size_t)blockIdx.x * blockDim.x + threadIdx.x;
    if (idx >= (size_t)MXG * KXG) return;
    int c = idx % KXG;
    int r = idx / KXG;            // r = t*256 + b
    int t = r >> 8, b = r & 255;
    int d, want_lo = 0;
    if (c < 416)       { d = c; }
    else if (c < 832)  { d = c - 416; want_lo = 1; }
    else if (c < 1248) { d = c - 832; }
    else               { g_xbf[idx] = __float2half_rn(0.f); return; }
    float v = 0.f;
    int bt = b * Tn + t;
    if (d < 300)       v = xt[(size_t)bt * 300 + d];
    else if (d < 374)  v = xa[(size_t)bt * 74 + (d - 300)];
    else if (d < 409)  v = xv[(size_t)bt * 35 + (d - 374)];
    __half hi = __float2half_rn(v);
    g_xbf[idx] = want_lo ? __float2half_rn(v - __half2float(hi)) : hi;
}

__global__ void prep_w(const float* __restrict__ Whh) {
    size_t idx = (size_t)blockIdx.x * blockDim.x + threadIdx.x;
    if (idx >= (size_t)G4 * KST) return;
    int c = idx % KST;
    int rp = idx / KST;                 // rp = 4k + g
    int k = rp >> 2, g = rp & 3;
    const float* row = Whh + (size_t)(g * Hn + k) * Hn;
    float v; int lo = 0;
    if (c < 1024)       v = row[c];
    else if (c < 2048)  v = row[c - 1024];
    else              { v = row[c - 2048]; lo = 1; }
    __half hi = __float2half_rn(v);
    g_W[idx] = lo ? __float2half_rn(v - __half2float(hi)) : hi;
}

__global__ void prep_wx(const float* __restrict__ Wih) {
    size_t idx = (size_t)blockIdx.x * blockDim.x + threadIdx.x;
    if (idx >= (size_t)G4 * KXG) return;
    int c = idx % KXG;
    int rp = idx / KXG;
    int k = rp >> 2, g = rp & 3;
    int d, lo = 0;
    if (c < 416)       d = c;
    else if (c < 832)  d = c - 416;
    else if (c < 1248) { d = c - 832; lo = 1; }
    else { g_Wx[idx] = __float2half_rn(0.f); return; }
    float v = (d < Dn) ? Wih[(size_t)(g * Hn + k) * Dn + d] : 0.f;
    __half hi = __float2half_rn(v);
    g_Wx[idx] = lo ? __float2half_rn(v - __half2float(hi)) : hi;
}

__global__ void prep_bias(const float* __restrict__ bih, const float* __restrict__ bhh) {
    int o = blockIdx.x * blockDim.x + threadIdx.x;
    if (o >= G4) return;
    int k = o >> 2, g = o & 3;
    g_bias[o] = bih[g * Hn + k] + bhh[g * Hn + k];
}

__global__ void init_state() {
    int idx = blockIdx.x * blockDim.x + threadIdx.x;
    if (idx < Bn * Hn) {
        g_hhi[0][idx] = __float2half_rn(0.f);
        g_hlo[0][idx] = __float2half_rn(0.f);
        g_c[idx] = 0.f;
    }
}

// ---------------- xg GEMM: g_xg = x_split @ Wx_split^T + bias ------------------
// M=65536 (BM=64), N=4096 (BN=128), K=1280 (BK=64, 20 iters). 256 thr, 8 warps.
__global__ __launch_bounds__(256)
void xg_gemm() {
    extern __shared__ char smem[];
    const uint32_t sb = s2u(smem);
    const int tid = threadIdx.x;
    const int lane = tid & 31, wid = tid >> 5;
    const int wm = wid & 1, wn = wid >> 1;
    const int n0 = blockIdx.x * 128;
    const int m0 = blockIdx.y * 64;

    uint32_t dA[2], dB[4];
#pragma unroll
    for (int i = 0; i < 2; i++) { int ch = tid + i * 256; dA[i] = SW128(((ch >> 3) << 7) + (ch & 7) * 16); }
#pragma unroll
    for (int i = 0; i < 4; i++) { int ch = tid + i * 256; dB[i] = 8192 + SW128(((ch >> 3) << 7) + (ch & 7) * 16); }

    uint32_t offA[2][4], offB[2][4];
#pragma unroll
    for (int mi = 0; mi < 2; mi++)
#pragma unroll
        for (int k = 0; k < 4; k++)
            offA[mi][k] = SW128((wm * 32 + mi * 16 + (lane & 15)) * 128 + k * 32 + (lane >> 4) * 16);
#pragma unroll
    for (int bj = 0; bj < 2; bj++)
#pragma unroll
        for (int k = 0; k < 4; k++)
            offB[bj][k] = 8192 + SW128((wn * 32 + bj * 16 + (lane & 15)) * 128 + k * 32 + (lane >> 4) * 16);

    float acc[2][4][4];
#pragma unroll
    for (int i = 0; i < 2; i++)
#pragma unroll
        for (int j = 0; j < 4; j++)
#pragma unroll
            for (int q = 0; q < 4; q++) acc[i][j][q] = 0.f;

    auto load_tile = [&](int j) {
        const uint32_t base = sb + (j % 3) * STGB;
#pragma unroll
        for (int i = 0; i < 2; i++) {
            int ch = tid + i * 256; int row = ch >> 3, cc = ch & 7;
            cp16(base + dA[i], g_xbf + (size_t)(m0 + row) * KXG + j * 64 + cc * 8);
        }
#pragma unroll
        for (int i = 0; i < 4; i++) {
            int ch = tid + i * 256; int row = ch >> 3, cc = ch & 7;
            cp16(base + dB[i], g_Wx + (size_t)(n0 + row) * KXG + j * 64 + cc * 8);
        }
        cp_commit();
    };

    load_tile(0); load_tile(1); load_tile(2);
    const int NT = KXG / 64;
    for (int kt = 0; kt < NT; kt++) {
        cp_wait2();
        __syncthreads();
        const uint32_t base = sb + (kt % 3) * STGB;
#pragma unroll
        for (int k16 = 0; k16 < 4; k16++) {
            uint32_t a[2][4], b[2][4];
            ldsm4(a[0][0], a[0][1], a[0][2], a[0][3], base + offA[0][k16]);
            ldsm4(a[1][0], a[1][1], a[1][2], a[1][3], base + offA[1][k16]);
            ldsm4(b[0][0], b[0][1], b[0][2], b[0][3], base + offB[0][k16]);
            ldsm4(b[1][0], b[1][1], b[1][2], b[1][3], base + offB[1][k16]);
#pragma unroll
            for (int mi = 0; mi < 2; mi++) {
                mma16816(acc[mi][0], a[mi], b[0][0], b[0][2]);
                mma16816(acc[mi][1], a[mi], b[0][1], b[0][3]);
                mma16816(acc[mi][2], a[mi], b[1][0], b[1][2]);
                mma16816(acc[mi][3], a[mi], b[1][1], b[1][3]);
            }
        }
        __syncthreads();
        if (kt + 3 < NT) load_tile(kt + 3); else cp_commit();
    }

    // epilogue: stage in SMEM, add bias, write fp32
    float* sg = (float*)smem;             // [64][132]
#pragma unroll
    for (int mi = 0; mi < 2; mi++)
#pragma unroll
        for (int nj = 0; nj < 4; nj++) {
            int row = wm * 32 + mi * 16 + (lane >> 2);
            int col = wn * 32 + nj * 8 + (lane & 3) * 2;
            sg[row * 132 + col]       = acc[mi][nj][0];
            sg[row * 132 + col + 1]   = acc[mi][nj][1];
            sg[(row + 8) * 132 + col]     = acc[mi][nj][2];
            sg[(row + 8) * 132 + col + 1] = acc[mi][nj][3];
        }
    __syncthreads();
#pragma unroll
    for (int i = 0; i < 8; i++) {
        int idx = tid + i * 256;          // 0..2047
        int c4 = idx & 31, row = idx >> 5;
        float4 v = *(float4*)&sg[row * 132 + c4 * 4];
        float4 bz = *(const float4*)&g_bias[n0 + c4 * 4];
        v.x += bz.x; v.y += bz.y; v.z += bz.z; v.w += bz.w;
        *(float4*)(g_xg + (size_t)(m0 + row) * G4 + n0 + c4 * 4) = v;
    }
}

// ---------------- fused step: gates GEMM + LSTM update -------------------------
// M=256 (BM=64), N=4096 (BN=128), K=3072 (48 iters). grid (32,4)=128 CTAs.
__global__ __launch_bounds__(256)
void step_kernel(int t) {
    extern __shared__ char smem[];
    const uint32_t sb = s2u(smem);
    const int tid = threadIdx.x;
    const int lane = tid & 31, wid = tid >> 5;
    const int wm = wid & 1, wn = wid >> 1;
    const int n0 = blockIdx.x * 128;
    const int m0 = blockIdx.y * 64;
    const int p = t & 1;
    const __half* __restrict__ hhi = g_hhi[p];
    const __half* __restrict__ hlo = g_hlo[p];

    uint32_t dA[2], dB[4];
#pragma unroll
    for (int i = 0; i < 2; i++) { int ch = tid + i * 256; dA[i] = SW128(((ch >> 3) << 7) + (ch & 7) * 16); }
#pragma unroll
    for (int i = 0; i < 4; i++) { int ch = tid + i * 256; dB[i] = 8192 + SW128(((ch >> 3) << 7) + (ch & 7) * 16); }

    uint32_t offA[2][4], offB[2][4];
#pragma unroll
    for (int mi = 0; mi < 2; mi++)
#pragma unroll
        for (int k = 0; k < 4; k++)
            offA[mi][k] = SW128((wm * 32 + mi * 16 + (lane & 15)) * 128 + k * 32 + (lane >> 4) * 16);
#pragma unroll
    for (int bj = 0; bj < 2; bj++)
#pragma unroll
        for (int k = 0; k < 4; k++)
            offB[bj][k] = 8192 + SW128((wn * 32 + bj * 16 + (lane & 15)) * 128 + k * 32 + (lane >> 4) * 16);

    float acc[2][4][4];
#pragma unroll
    for (int i = 0; i < 2; i++)
#pragma unroll
        for (int j = 0; j < 4; j++)
#pragma unroll
            for (int q = 0; q < 4; q++) acc[i][j][q] = 0.f;

    auto load_tile = [&](int j) {
        const uint32_t base = sb + (j % 3) * STGB;
        const int blk = j >> 4;              // 0:hi 1:lo 2:hi
        const int kc = (j & 15) * 64;
        const __half* asrc = (blk == 1) ? hlo : hhi;
#pragma unroll
        for (int i = 0; i < 2; i++) {
            int ch = tid + i * 256; int row = ch >> 3, cc = ch & 7;
            cp16(base + dA[i], asrc + (size_t)(m0 + row) * Hn + kc + cc * 8);
        }
#pragma unroll
        for (int i = 0; i < 4; i++) {
            int ch = tid + i * 256; int row = ch >> 3, cc = ch & 7;
            cp16(base + dB[i], g_W + (size_t)(n0 + row) * KST + j * 64 + cc * 8);
        }
        cp_commit();
    };

    load_tile(0); load_tile(1); load_tile(2);
    const int NT = KST / 64;
    for (int kt = 0; kt < NT; kt++) {
        cp_wait2();
        __syncthreads();
        const uint32_t base = sb + (kt % 3) * STGB;
#pragma unroll
        for (int k16 = 0; k16 < 4; k16++) {
            uint32_t a[2][4], b[2][4];
            ldsm4(a[0][0], a[0][1], a[0][2], a[0][3], base + offA[0][k16]);
            ldsm4(a[1][0], a[1][1], a[1][2], a[1][3], base + offA[1][k16]);
            ldsm4(b[0][0], b[0][1], b[0][2], b[0][3], base + offB[0][k16]);
            ldsm4(b[1][0], b[1][1], b[1][2], b[1][3], base + offB[1][k16]);
#pragma unroll
            for (int mi = 0; mi < 2; mi++) {
                mma16816(acc[mi][0], a[mi], b[0][0], b[0][2]);
                mma16816(acc[mi][1], a[mi], b[0][1], b[0][3]);
                mma16816(acc[mi][2], a[mi], b[1][0], b[1][2]);
                mma16816(acc[mi][3], a[mi], b[1][1], b[1][3]);
            }
        }
        __syncthreads();
        if (kt + 3 < NT) load_tile(kt + 3); else cp_commit();
    }

    // ---- fused LSTM epilogue: cols are gate-interleaved p = 4k+g ----
    float* sg = (float*)smem;             // [64][132]
#pragma unroll
    for (int mi = 0; mi < 2; mi++)
#pragma unroll
        for (int nj = 0; nj < 4; nj++) {
            int row = wm * 32 + mi * 16 + (lane >> 2);
            int col = wn * 32 + nj * 8 + (lane & 3) * 2;
            sg[row * 132 + col]       = acc[mi][nj][0];
            sg[row * 132 + col + 1]   = acc[mi][nj][1];
            sg[(row + 8) * 132 + col]     = acc[mi][nj][2];
            sg[(row + 8) * 132 + col + 1] = acc[mi][nj][3];
        }
    __syncthreads();

    __half* __restrict__ ohi = g_hhi[p ^ 1];
    __half* __restrict__ olo = g_hlo[p ^ 1];
#pragma unroll
    for (int i = 0; i < 8; i++) {
        int idx = tid + i * 256;          // 0..2047 : 64 rows x 32 units
        int u = idx & 31, row = idx >> 5;
        float4 gv4 = *(float4*)&sg[row * 132 + u * 4];
        float4 xv = *(const float4*)(g_xg + ((size_t)t * Bn + m0 + row) * G4 + n0 + u * 4);
        float iv = sigf(gv4.x + xv.x);
        float fv = sigf(gv4.y + xv.y);
        float gg = tanhf(gv4.z + xv.z);
        float ov = sigf(gv4.w + xv.w);
        int ci = (m0 + row) * Hn + (n0 >> 2) + u;
        float cn = fv * g_c[ci] + iv * gg;
        g_c[ci] = cn;
        float h = ov * tanhf(cn);
        __half hi = __float2half_rn(h);
        ohi[ci] = hi;
        olo[ci] = __float2half_rn(h - __half2float(hi));
    }
}

// ---------------- MLP head -----------------------------------------------------
__global__ __launch_bounds__(256)
void mlp_kernel(const float* __restrict__ W1, const float* __restrict__ b1,
                const float* __restrict__ W2, const float* __restrict__ b2,
                float* __restrict__ out) {
    __shared__ __align__(16) float hs[Hn];
    __shared__ float hid[512];
    __shared__ float red[256];
    int bb = blockIdx.x, tid = threadIdx.x;
    for (int i = tid; i < Hn; i += 256)
        hs[i] = __half2float(g_hhi[0][bb * Hn + i]) + __half2float(g_hlo[0][bb * Hn + i]);
    __syncthreads();
    for (int j = tid; j < 512; j += 256) {
        const float4* w = (const float4*)(W1 + j * Hn);
        float s = 0.f;
#pragma unroll 8
        for (int k = 0; k < Hn / 4; k++) {
            float4 w4 = w[k];
            s += w4.x * hs[4 * k] + w4.y * hs[4 * k + 1] + w4.z * hs[4 * k + 2] + w4.w * hs[4 * k + 3];
        }
        s += b1[j];
        hid[j] = s > 0.f ? s : 0.f;
    }
    __syncthreads();
    red[tid] = hid[tid] * W2[tid] + hid[tid + 256] * W2[tid + 256];
    __syncthreads();
    for (int s = 128; s > 0; s >>= 1) {
        if (tid < s) red[tid] += red[tid + s];
        __syncthreads();
    }
    if (tid == 0) out[bb] = red[0] + b2[0];
}

// ---------------- launch -------------------------------------------------------
extern "C" void kernel_launch(void* const* d_in, const int* in_sizes, int n_in,
                              void* d_out, int out_size) {
    const float* x_text   = (const float*)d_in[0];
    const float* x_audio  = (const float*)d_in[1];
    const float* x_vision = (const float*)d_in[2];
    const float* W_ih     = (const float*)d_in[3];
    const float* W_hh     = (const float*)d_in[4];
    const float* b_ih     = (const float*)d_in[5];
    const float* b_hh     = (const float*)d_in[6];
    const float* W1       = (const float*)d_in[7];
    const float* b1       = (const float*)d_in[8];
    const float* W2       = (const float*)d_in[9];
    const float* b2       = (const float*)d_in[10];
    float* out = (float*)d_out;

    cudaFuncSetAttribute(xg_gemm, cudaFuncAttributeMaxDynamicSharedMemorySize, SMEMSZ);
    cudaFuncSetAttribute(step_kernel, cudaFuncAttributeMaxDynamicSharedMemorySize, SMEMSZ);

    {
        size_t n = (size_t)MXG * KXG;
        prep_x<<<(unsigned)((n + 255) / 256), 256>>>(x_text, x_audio, x_vision);
    }
    {
        size_t n = (size_t)G4 * KST;
        prep_w<<<(unsigned)((n + 255) / 256), 256>>>(W_hh);
    }
    {
        size_t n = (size_t)G4 * KXG;
        prep_wx<<<(unsigned)((n + 255) / 256), 256>>>(W_ih);
    }
    prep_bias<<<G4 / 256, 256>>>(b_ih, b_hh);
    init_state<<<(Bn * Hn + 255) / 256, 256>>>();

    xg_gemm<<<dim3(G4 / 128, MXG / 64), 256, SMEMSZ>>>();

    for (int t = 0; t < Tn; t++)
        step_kernel<<<dim3(G4 / 128, Bn / 64), 256, SMEMSZ>>>(t);

    mlp_kernel<<<Bn, 256>>>(W1, b1, W2, b2, out);
}

// round 6
// speedup vs baseline: 3.8106x; 2.1035x over previous
#include <cuda_runtime.h>
#include <cuda_fp16.h>
#include <cstdint>

#define Bn 256
#define Tn 256
#define Hn 1024
#define G4 4096
#define Dn 409
#define KXG 1280          // xg: 3*416=1248 padded to 1280 (3-term kept)
#define MXG 65536         // B*T
#define BM 64
#define BN 128
#define NT 16             // k-tiles of 64 over K=1024 (B side)
#define NCTA 128          // (4096/BN) * (256/BM) = 32*4

// ---------------- device scratch ----------------------------------------------
__device__ __align__(16) __half g_W[(size_t)G4 * Hn];       // 8 MB  fp16(Whh) gate-interleaved
__device__ __align__(16) __half g_Wx[(size_t)G4 * KXG];     // 10 MB
__device__ __align__(16) __half g_xbf[(size_t)MXG * KXG];   // 160 MB
__device__ float g_xg[(size_t)MXG * G4];                    // 1 GiB
__device__ __align__(16) __half g_hhi[2][Bn * Hn];
__device__ __align__(16) __half g_hlo[2][Bn * Hn];
__device__ float g_c[Bn * Hn];
__device__ float g_bias[G4];
__device__ int g_bar;                                       // persistent barrier counter

// ---------------- PTX helpers ---------------------------------------------------
__device__ __forceinline__ uint32_t s2u(const void* p) {
    uint32_t a;
    asm("{ .reg .u64 t; cvta.to.shared.u64 t, %1; cvt.u32.u64 %0, t; }" : "=r"(a) : "l"(p));
    return a;
}
__device__ __forceinline__ void cp16(uint32_t dst, const void* src) {
    asm volatile("cp.async.cg.shared.global [%0], [%1], 16;" :: "r"(dst), "l"(src));
}
__device__ __forceinline__ void cp_commit() { asm volatile("cp.async.commit_group;"); }
__device__ __forceinline__ void cp_wait2() { asm volatile("cp.async.wait_group 2;" ::: "memory"); }

__device__ __forceinline__ void ldsm4(uint32_t& r0, uint32_t& r1, uint32_t& r2, uint32_t& r3,
                                      uint32_t addr) {
    asm volatile("ldmatrix.sync.aligned.m8n8.x4.shared.b16 {%0,%1,%2,%3}, [%4];"
                 : "=r"(r0), "=r"(r1), "=r"(r2), "=r"(r3) : "r"(addr));
}
__device__ __forceinline__ void mma16816(float* d, const uint32_t* a, uint32_t b0, uint32_t b1) {
    asm volatile(
        "mma.sync.aligned.m16n8k16.row.col.f32.f16.f16.f32 "
        "{%0,%1,%2,%3}, {%4,%5,%6,%7}, {%8,%9}, {%0,%1,%2,%3};"
        : "+f"(d[0]), "+f"(d[1]), "+f"(d[2]), "+f"(d[3])
        : "r"(a[0]), "r"(a[1]), "r"(a[2]), "r"(a[3]), "r"(b0), "r"(b1));
}

#define SW128(o) ((o) ^ (((o) >> 3) & 0x70))
// persistent stage: A_hi 8KB @0, A_lo 8KB @8192, B 16KB @16384 -> 32KB; 4 stages
#define PST 32768
#define PSMEM (4 * PST)
// xg gemm stage (unchanged from R5): A 8KB + B 16KB
#define STGB 24576
#define XSMEM (3 * STGB)

__device__ __forceinline__ float sigf(float x) { return 1.f / (1.f + expf(-x)); }

// ---------------- prep kernels --------------------------------------------------
__global__ void prep_x(const float* __restrict__ xt, const float* __restrict__ xa,
                       const float* __restrict__ xv) {
    size_t idx = (size_t)blockIdx.x * blockDim.x + threadIdx.x;
    if (idx >= (size_t)MXG * KXG) return;
    int c = idx % KXG;
    int r = idx / KXG;            // r = t*256 + b
    int t = r >> 8, b = r & 255;
    int d, want_lo = 0;
    if (c < 416)       { d = c; }
    else if (c < 832)  { d = c - 416; want_lo = 1; }
    else if (c < 1248) { d = c - 832; }
    else               { g_xbf[idx] = __float2half_rn(0.f); return; }
    float v = 0.f;
    int bt = b * Tn + t;
    if (d < 300)       v = xt[(size_t)bt * 300 + d];
    else if (d < 374)  v = xa[(size_t)bt * 74 + (d - 300)];
    else if (d < 409)  v = xv[(size_t)bt * 35 + (d - 374)];
    __half hi = __float2half_rn(v);
    g_xbf[idx] = want_lo ? __float2half_rn(v - __half2float(hi)) : hi;
}

// g_W[p][k] = fp16(Whh[gate*Hn + unit][k]),  p = 4*unit + gate
__global__ void prep_w(const float* __restrict__ Whh) {
    size_t idx = (size_t)blockIdx.x * blockDim.x + threadIdx.x;
    if (idx >= (size_t)G4 * Hn) return;
    int c = idx % Hn;
    int rp = idx / Hn;
    int k = rp >> 2, g = rp & 3;
    g_W[idx] = __float2half_rn(Whh[(size_t)(g * Hn + k) * Hn + c]);
}

__global__ void prep_wx(const float* __restrict__ Wih) {
    size_t idx = (size_t)blockIdx.x * blockDim.x + threadIdx.x;
    if (idx >= (size_t)G4 * KXG) return;
    int c = idx % KXG;
    int rp = idx / KXG;
    int k = rp >> 2, g = rp & 3;
    int d, lo = 0;
    if (c < 416)       d = c;
    else if (c < 832)  d = c - 416;
    else if (c < 1248) { d = c - 832; lo = 1; }
    else { g_Wx[idx] = __float2half_rn(0.f); return; }
    float v = (d < Dn) ? Wih[(size_t)(g * Hn + k) * Dn + d] : 0.f;
    __half hi = __float2half_rn(v);
    g_Wx[idx] = lo ? __float2half_rn(v - __half2float(hi)) : hi;
}

__global__ void prep_bias(const float* __restrict__ bih, const float* __restrict__ bhh) {
    int o = blockIdx.x * blockDim.x + threadIdx.x;
    if (o >= G4) return;
    int k = o >> 2, g = o & 3;
    g_bias[o] = bih[g * Hn + k] + bhh[g * Hn + k];
}

__global__ void init_state() {
    int idx = blockIdx.x * blockDim.x + threadIdx.x;
    if (idx == 0) g_bar = 0;
    if (idx < Bn * Hn) {
        g_hhi[0][idx] = __float2half_rn(0.f);
        g_hlo[0][idx] = __float2half_rn(0.f);
        g_c[idx] = 0.f;
    }
}

// ---------------- xg GEMM (unchanged from R5, proven) ---------------------------
__global__ __launch_bounds__(256)
void xg_gemm() {
    extern __shared__ char smem[];
    const uint32_t sb = s2u(smem);
    const int tid = threadIdx.x;
    const int lane = tid & 31, wid = tid >> 5;
    const int wm = wid & 1, wn = wid >> 1;
    const int n0 = blockIdx.x * 128;
    const int m0 = blockIdx.y * 64;

    uint32_t dA[2], dB[4];
#pragma unroll
    for (int i = 0; i < 2; i++) { int ch = tid + i * 256; dA[i] = SW128(((ch >> 3) << 7) + (ch & 7) * 16); }
#pragma unroll
    for (int i = 0; i < 4; i++) { int ch = tid + i * 256; dB[i] = 8192 + SW128(((ch >> 3) << 7) + (ch & 7) * 16); }

    uint32_t offA[2][4], offB[2][4];
#pragma unroll
    for (int mi = 0; mi < 2; mi++)
#pragma unroll
        for (int k = 0; k < 4; k++)
            offA[mi][k] = SW128((wm * 32 + mi * 16 + (lane & 15)) * 128 + k * 32 + (lane >> 4) * 16);
#pragma unroll
    for (int bj = 0; bj < 2; bj++)
#pragma unroll
        for (int k = 0; k < 4; k++)
            offB[bj][k] = 8192 + SW128((wn * 32 + bj * 16 + (lane & 15)) * 128 + k * 32 + (lane >> 4) * 16);

    float acc[2][4][4];
#pragma unroll
    for (int i = 0; i < 2; i++)
#pragma unroll
        for (int j = 0; j < 4; j++)
#pragma unroll
            for (int q = 0; q < 4; q++) acc[i][j][q] = 0.f;

    auto load_tile = [&](int j) {
        const uint32_t base = sb + (j % 3) * STGB;
#pragma unroll
        for (int i = 0; i < 2; i++) {
            int ch = tid + i * 256; int row = ch >> 3, cc = ch & 7;
            cp16(base + dA[i], g_xbf + (size_t)(m0 + row) * KXG + j * 64 + cc * 8);
        }
#pragma unroll
        for (int i = 0; i < 4; i++) {
            int ch = tid + i * 256; int row = ch >> 3, cc = ch & 7;
            cp16(base + dB[i], g_Wx + (size_t)(n0 + row) * KXG + j * 64 + cc * 8);
        }
        cp_commit();
    };

    load_tile(0); load_tile(1); load_tile(2);
    const int NTX = KXG / 64;
    for (int kt = 0; kt < NTX; kt++) {
        cp_wait2();
        __syncthreads();
        const uint32_t base = sb + (kt % 3) * STGB;
#pragma unroll
        for (int k16 = 0; k16 < 4; k16++) {
            uint32_t a[2][4], b[2][4];
            ldsm4(a[0][0], a[0][1], a[0][2], a[0][3], base + offA[0][k16]);
            ldsm4(a[1][0], a[1][1], a[1][2], a[1][3], base + offA[1][k16]);
            ldsm4(b[0][0], b[0][1], b[0][2], b[0][3], base + offB[0][k16]);
            ldsm4(b[1][0], b[1][1], b[1][2], b[1][3], base + offB[1][k16]);
#pragma unroll
            for (int mi = 0; mi < 2; mi++) {
                mma16816(acc[mi][0], a[mi], b[0][0], b[0][2]);
                mma16816(acc[mi][1], a[mi], b[0][1], b[0][3]);
                mma16816(acc[mi][2], a[mi], b[1][0], b[1][2]);
                mma16816(acc[mi][3], a[mi], b[1][1], b[1][3]);
            }
        }
        __syncthreads();
        if (kt + 3 < NTX) load_tile(kt + 3); else cp_commit();
    }

    float* sg = (float*)smem;             // [64][132]
#pragma unroll
    for (int mi = 0; mi < 2; mi++)
#pragma unroll
        for (int nj = 0; nj < 4; nj++) {
            int row = wm * 32 + mi * 16 + (lane >> 2);
            int col = wn * 32 + nj * 8 + (lane & 3) * 2;
            sg[row * 132 + col]       = acc[mi][nj][0];
            sg[row * 132 + col + 1]   = acc[mi][nj][1];
            sg[(row + 8) * 132 + col]     = acc[mi][nj][2];
            sg[(row + 8) * 132 + col + 1] = acc[mi][nj][3];
        }
    __syncthreads();
#pragma unroll
    for (int i = 0; i < 8; i++) {
        int idx = tid + i * 256;
        int c4 = idx & 31, row = idx >> 5;
        float4 v = *(float4*)&sg[row * 132 + c4 * 4];
        float4 bz = *(const float4*)&g_bias[n0 + c4 * 4];
        v.x += bz.x; v.y += bz.y; v.z += bz.z; v.w += bz.w;
        *(float4*)(g_xg + (size_t)(m0 + row) * G4 + n0 + c4 * 4) = v;
    }
}

// ---------------- persistent recurrence kernel ----------------------------------
// grid (32, 4) = 128 CTAs, 1/SM, all 256 steps, global barrier between steps.
// gates = h_hi @ W16 + h_lo @ W16 (shared B tile), K=1024, NT=16 iters of 64.
__global__ __launch_bounds__(256)
void persist_kernel() {
    extern __shared__ char smem[];
    const uint32_t sb = s2u(smem);
    const int tid = threadIdx.x;
    const int lane = tid & 31, wid = tid >> 5;
    const int wm = wid & 1, wn = wid >> 1;
    const int n0 = blockIdx.x * BN;
    const int m0 = blockIdx.y * BM;

    // cp.async dst offsets (within stage): A_hi 2/thr, A_lo 2/thr, B 4/thr
    uint32_t dAh[2], dAl[2], dB[4];
#pragma unroll
    for (int i = 0; i < 2; i++) {
        int ch = tid + i * 256;
        uint32_t o = SW128(((ch >> 3) << 7) + (ch & 7) * 16);
        dAh[i] = o; dAl[i] = 8192 + o;
    }
#pragma unroll
    for (int i = 0; i < 4; i++) {
        int ch = tid + i * 256;
        dB[i] = 16384 + SW128(((ch >> 3) << 7) + (ch & 7) * 16);
    }

    uint32_t offAh[2][4], offAl[2][4], offB[2][4];
#pragma unroll
    for (int mi = 0; mi < 2; mi++)
#pragma unroll
        for (int k = 0; k < 4; k++) {
            uint32_t o = SW128((wm * 32 + mi * 16 + (lane & 15)) * 128 + k * 32 + (lane >> 4) * 16);
            offAh[mi][k] = o; offAl[mi][k] = 8192 + o;
        }
#pragma unroll
    for (int bj = 0; bj < 2; bj++)
#pragma unroll
        for (int k = 0; k < 4; k++)
            offB[bj][k] = 16384 + SW128((wn * 32 + bj * 16 + (lane & 15)) * 128 + k * 32 + (lane >> 4) * 16);

    for (int t = 0; t < Tn; t++) {
        const int p = t & 1;
        const __half* __restrict__ hhi = g_hhi[p];
        const __half* __restrict__ hlo = g_hlo[p];

        auto load_tile = [&](int j) {
            const uint32_t base = sb + (j & 3) * PST;
            const int kc = j * 64;
#pragma unroll
            for (int i = 0; i < 2; i++) {
                int ch = tid + i * 256; int row = ch >> 3, cc = ch & 7;
                cp16(base + dAh[i], hhi + (size_t)(m0 + row) * Hn + kc + cc * 8);
                cp16(base + dAl[i], hlo + (size_t)(m0 + row) * Hn + kc + cc * 8);
            }
#pragma unroll
            for (int i = 0; i < 4; i++) {
                int ch = tid + i * 256; int row = ch >> 3, cc = ch & 7;
                cp16(base + dB[i], g_W + (size_t)(n0 + row) * Hn + kc + cc * 8);
            }
            cp_commit();
        };

        float acc[2][4][4];
#pragma unroll
        for (int i = 0; i < 2; i++)
#pragma unroll
            for (int j = 0; j < 4; j++)
#pragma unroll
                for (int q = 0; q < 4; q++) acc[i][j][q] = 0.f;

        load_tile(0); load_tile(1); load_tile(2);
        for (int kt = 0; kt < NT; kt++) {
            cp_wait2();
            __syncthreads();
            const uint32_t base = sb + (kt & 3) * PST;
#pragma unroll
            for (int k16 = 0; k16 < 4; k16++) {
                uint32_t ah[2][4], al[2][4], b[2][4];
                ldsm4(ah[0][0], ah[0][1], ah[0][2], ah[0][3], base + offAh[0][k16]);
                ldsm4(ah[1][0], ah[1][1], ah[1][2], ah[1][3], base + offAh[1][k16]);
                ldsm4(al[0][0], al[0][1], al[0][2], al[0][3], base + offAl[0][k16]);
                ldsm4(al[1][0], al[1][1], al[1][2], al[1][3], base + offAl[1][k16]);
                ldsm4(b[0][0], b[0][1], b[0][2], b[0][3], base + offB[0][k16]);
                ldsm4(b[1][0], b[1][1], b[1][2], b[1][3], base + offB[1][k16]);
#pragma unroll
                for (int mi = 0; mi < 2; mi++) {
                    mma16816(acc[mi][0], ah[mi], b[0][0], b[0][2]);
                    mma16816(acc[mi][1], ah[mi], b[0][1], b[0][3]);
                    mma16816(acc[mi][2], ah[mi], b[1][0], b[1][2]);
                    mma16816(acc[mi][3], ah[mi], b[1][1], b[1][3]);
                    mma16816(acc[mi][0], al[mi], b[0][0], b[0][2]);
                    mma16816(acc[mi][1], al[mi], b[0][1], b[0][3]);
                    mma16816(acc[mi][2], al[mi], b[1][0], b[1][2]);
                    mma16816(acc[mi][3], al[mi], b[1][1], b[1][3]);
                }
            }
            if (kt + 3 < NT) load_tile(kt + 3); else cp_commit();
        }
        __syncthreads();   // all warps done with smem stages before sg overwrite

        // ---- epilogue: accum -> smem -> LSTM update ----
        float* sg = (float*)smem;         // [64][132] = 33792 B (stages 0..1 region)
#pragma unroll
        for (int mi = 0; mi < 2; mi++)
#pragma unroll
            for (int nj = 0; nj < 4; nj++) {
                int row = wm * 32 + mi * 16 + (lane >> 2);
                int col = wn * 32 + nj * 8 + (lane & 3) * 2;
                sg[row * 132 + col]       = acc[mi][nj][0];
                sg[row * 132 + col + 1]   = acc[mi][nj][1];
                sg[(row + 8) * 132 + col]     = acc[mi][nj][2];
                sg[(row + 8) * 132 + col + 1] = acc[mi][nj][3];
            }
        __syncthreads();

        __half* __restrict__ ohi = g_hhi[p ^ 1];
        __half* __restrict__ olo = g_hlo[p ^ 1];
#pragma unroll
        for (int i = 0; i < 8; i++) {
            int idx = tid + i * 256;      // 64 rows x 32 units
            int u = idx & 31, row = idx >> 5;
            float4 gv4 = *(float4*)&sg[row * 132 + u * 4];
            float4 xv = *(const float4*)(g_xg + ((size_t)t * Bn + m0 + row) * G4 + n0 + u * 4);
            float iv = sigf(gv4.x + xv.x);
            float fv = sigf(gv4.y + xv.y);
            float gg = tanhf(gv4.z + xv.z);
            float ov = sigf(gv4.w + xv.w);
            int ci = (m0 + row) * Hn + (n0 >> 2) + u;
            float cn = fv * g_c[ci] + iv * gg;
            g_c[ci] = cn;
            float h = ov * tanhf(cn);
            __half hi = __float2half_rn(h);
            ohi[ci] = hi;
            olo[ci] = __float2half_rn(h - __half2float(hi));
        }

        // ---- global barrier (monotonic counter; reset by init_state each launch) ----
        __threadfence();
        __syncthreads();
        if (tid == 0) {
            atomicAdd(&g_bar, 1);
            while (*((volatile int*)&g_bar) < NCTA * (t + 1)) { }
            __threadfence();
        }
        __syncthreads();
    }
}

// ---------------- MLP head ------------------------------------------------------
__global__ __launch_bounds__(256)
void mlp_kernel(const float* __restrict__ W1, const float* __restrict__ b1,
                const float* __restrict__ W2, const float* __restrict__ b2,
                float* __restrict__ out) {
    __shared__ __align__(16) float hs[Hn];
    __shared__ float hid[512];
    __shared__ float red[256];
    int bb = blockIdx.x, tid = threadIdx.x;
    for (int i = tid; i < Hn; i += 256)
        hs[i] = __half2float(g_hhi[0][bb * Hn + i]) + __half2float(g_hlo[0][bb * Hn + i]);
    __syncthreads();
    for (int j = tid; j < 512; j += 256) {
        const float4* w = (const float4*)(W1 + j * Hn);
        float s = 0.f;
#pragma unroll 8
        for (int k = 0; k < Hn / 4; k++) {
            float4 w4 = w[k];
            s += w4.x * hs[4 * k] + w4.y * hs[4 * k + 1] + w4.z * hs[4 * k + 2] + w4.w * hs[4 * k + 3];
        }
        s += b1[j];
        hid[j] = s > 0.f ? s : 0.f;
    }
    __syncthreads();
    red[tid] = hid[tid] * W2[tid] + hid[tid + 256] * W2[tid + 256];
    __syncthreads();
    for (int s = 128; s > 0; s >>= 1) {
        if (tid < s) red[tid] += red[tid + s];
        __syncthreads();
    }
    if (tid == 0) out[bb] = red[0] + b2[0];
}

// ---------------- launch --------------------------------------------------------
extern "C" void kernel_launch(void* const* d_in, const int* in_sizes, int n_in,
                              void* d_out, int out_size) {
    const float* x_text   = (const float*)d_in[0];
    const float* x_audio  = (const float*)d_in[1];
    const float* x_vision = (const float*)d_in[2];
    const float* W_ih     = (const float*)d_in[3];
    const float* W_hh     = (const float*)d_in[4];
    const float* b_ih     = (const float*)d_in[5];
    const float* b_hh     = (const float*)d_in[6];
    const float* W1       = (const float*)d_in[7];
    const float* b1       = (const float*)d_in[8];
    const float* W2       = (const float*)d_in[9];
    const float* b2       = (const float*)d_in[10];
    float* out = (float*)d_out;

    cudaFuncSetAttribute(xg_gemm, cudaFuncAttributeMaxDynamicSharedMemorySize, XSMEM);
    cudaFuncSetAttribute(persist_kernel, cudaFuncAttributeMaxDynamicSharedMemorySize, PSMEM);

    {
        size_t n = (size_t)MXG * KXG;
        prep_x<<<(unsigned)((n + 255) / 256), 256>>>(x_text, x_audio, x_vision);
    }
    {
        size_t n = (size_t)G4 * Hn;
        prep_w<<<(unsigned)((n + 255) / 256), 256>>>(W_hh);
    }
    {
        size_t n = (size_t)G4 * KXG;
        prep_wx<<<(unsigned)((n + 255) / 256), 256>>>(W_ih);
    }
    prep_bias<<<G4 / 256, 256>>>(b_ih, b_hh);
    init_state<<<(Bn * Hn + 255) / 256, 256>>>();

    xg_gemm<<<dim3(G4 / 128, MXG / 64), 256, XSMEM>>>();

    persist_kernel<<<dim3(G4 / BN, Bn / BM), 256, PSMEM>>>();

    mlp_kernel<<<Bn, 256>>>(W1, b1, W2, b2, out);
}